// round 4
// baseline (speedup 1.0000x reference)
#include <cuda_runtime.h>

// ---------------------------------------------------------------------------
// BettingLoss: per-row (B=4.19M rows, T=6 traps) expected-profit argmax +
// global reductions. Pure HBM-streaming workload: 302 MB read, 12 B written.
// ---------------------------------------------------------------------------

static __device__ double             g_sum_bet_ep;
static __device__ double             g_batch_profit;
static __device__ double             g_sum_maxprob;
static __device__ unsigned long long g_num_bets;

__global__ void init_acc_kernel() {
    g_sum_bet_ep   = 0.0;
    g_batch_profit = 0.0;
    g_sum_maxprob  = 0.0;
    g_num_bets     = 0ull;
}

// Process one race (6 traps). Arrays indexed with compile-time-constant
// offsets after unrolling -> stays in registers.
__device__ __forceinline__ void process_row(const float* __restrict__ p,
                                            const float* __restrict__ w,
                                            const float* __restrict__ o,
                                            float& ep_acc, float& pr_acc,
                                            float& mp_acc, int& nb)
{
    const float A   = 1.1f;    // ALPHA
    const float PAY = 0.019f;  // BET_PCT * (1 - COMMISSION)

    // ep_i = ((odds*1.1)*prob - 1) * 0.019  -- strict rounding, no contraction,
    // to match the reference's elementwise f32 arithmetic at the ep>0 boundary.
    float ep0  = __fmul_rn(__fsub_rn(__fmul_rn(__fmul_rn(o[0], A), p[0]), 1.0f), PAY);
    float best = ep0;
    float bo   = o[0];
    float bw   = w[0];
    float mx   = p[0];
    bool  valid = (o[0] > 0.0f);

#pragma unroll
    for (int i = 1; i < 6; ++i) {
        float ep = __fmul_rn(__fsub_rn(__fmul_rn(__fmul_rn(o[i], A), p[i]), 1.0f), PAY);
        if (ep > best) {       // strict '>' => first-max semantics like jnp.argmax
            best = ep; bo = o[i]; bw = w[i];
        }
        mx    = fmaxf(mx, p[i]);
        valid = valid || (o[i] > 0.0f);
    }

    mp_acc += mx;  // fallback term needs the row-max prob for ALL rows

    if (valid && best > 0.0f) {
        ep_acc += best;
        nb     += 1;
        // win_profit = ((odds*1.1)*0.02 - 0.02) * 0.95
        float win_profit = __fmul_rn(__fsub_rn(__fmul_rn(__fmul_rn(bo, A), 0.02f),
                                               0.02f), 0.95f);
        pr_acc += (bw > 0.5f) ? win_profit : -0.019f;
    }
}

__global__ void __launch_bounds__(256)
betting_loss_kernel(const float* __restrict__ probs,
                    const float* __restrict__ winners,
                    const float* __restrict__ odds,
                    long long pairs, long long rows)
{
    long long tid = (long long)blockIdx.x * blockDim.x + threadIdx.x;

    float ep_acc = 0.0f, pr_acc = 0.0f, mp_acc = 0.0f;
    int   nb = 0;

    if (tid < pairs) {
        // 2 rows = 12 floats = 48 B = 3 aligned float4 per array.
        long long v = tid * 3;
        const float4* __restrict__ P4 = (const float4*)probs;
        const float4* __restrict__ W4 = (const float4*)winners;
        const float4* __restrict__ O4 = (const float4*)odds;

        float4 pa = P4[v], pb = P4[v + 1], pc = P4[v + 2];
        float4 oa = O4[v], ob = O4[v + 1], oc = O4[v + 2];
        float4 wa = W4[v], wb = W4[v + 1], wc = W4[v + 2];

        float p[12] = {pa.x, pa.y, pa.z, pa.w, pb.x, pb.y, pb.z, pb.w,
                       pc.x, pc.y, pc.z, pc.w};
        float o[12] = {oa.x, oa.y, oa.z, oa.w, ob.x, ob.y, ob.z, ob.w,
                       oc.x, oc.y, oc.z, oc.w};
        float w[12] = {wa.x, wa.y, wa.z, wa.w, wb.x, wb.y, wb.z, wb.w,
                       wc.x, wc.y, wc.z, wc.w};

        process_row(p,     w,     o,     ep_acc, pr_acc, mp_acc, nb);
        process_row(p + 6, w + 6, o + 6, ep_acc, pr_acc, mp_acc, nb);
    }

    // Tail: if rows is odd, thread 0 handles the final unpaired row (scalar).
    if ((rows & 1) && tid == 0) {
        long long base = (rows - 1) * 6;
        float p[6], w[6], o[6];
#pragma unroll
        for (int i = 0; i < 6; ++i) {
            p[i] = probs[base + i];
            w[i] = winners[base + i];
            o[i] = odds[base + i];
        }
        process_row(p, w, o, ep_acc, pr_acc, mp_acc, nb);
    }

    // ---- reduction: warp shuffle (double) -> shared -> 1 atomic per block ----
    double de = (double)ep_acc;
    double dp = (double)pr_acc;
    double dm = (double)mp_acc;
    const unsigned full = 0xffffffffu;
#pragma unroll
    for (int off = 16; off > 0; off >>= 1) {
        de += __shfl_down_sync(full, de, off);
        dp += __shfl_down_sync(full, dp, off);
        dm += __shfl_down_sync(full, dm, off);
        nb += __shfl_down_sync(full, nb, off);
    }

    __shared__ double se[8], sp[8], sm[8];
    __shared__ int    sn[8];
    int warp = threadIdx.x >> 5;
    int lane = threadIdx.x & 31;
    if (lane == 0) { se[warp] = de; sp[warp] = dp; sm[warp] = dm; sn[warp] = nb; }
    __syncthreads();

    if (warp == 0) {
        int nw = blockDim.x >> 5;  // 8
        de = (lane < nw) ? se[lane] : 0.0;
        dp = (lane < nw) ? sp[lane] : 0.0;
        dm = (lane < nw) ? sm[lane] : 0.0;
        nb = (lane < nw) ? sn[lane] : 0;
#pragma unroll
        for (int off = 4; off > 0; off >>= 1) {
            de += __shfl_down_sync(full, de, off);
            dp += __shfl_down_sync(full, dp, off);
            dm += __shfl_down_sync(full, dm, off);
            nb += __shfl_down_sync(full, nb, off);
        }
        if (lane == 0) {
            atomicAdd(&g_sum_bet_ep,   de);
            atomicAdd(&g_batch_profit, dp);
            atomicAdd(&g_sum_maxprob,  dm);
            atomicAdd(&g_num_bets, (unsigned long long)nb);
        }
    }
}

__global__ void finalize_kernel(float* __restrict__ out, int out_size, double invB)
{
    double total = (g_num_bets > 0ull)
                       ? g_sum_bet_ep
                       : -(g_sum_maxprob * invB) * 0.1;  // fallback: -mean(maxprob)*0.1
    out[0] = (float)(-(total * invB));                   // loss
    if (out_size >= 3) {
        out[1] = (float)g_batch_profit;                  // batch_profit
        out[2] = (float)g_num_bets;                      // num_bets
    }
}

extern "C" void kernel_launch(void* const* d_in, const int* in_sizes, int n_in,
                              void* d_out, int out_size)
{
    const float* probs   = (const float*)d_in[0];  // predicted_probs [B,6]
    const float* winners = (const float*)d_in[1];  // true_winners    [B,6]
    const float* odds    = (const float*)d_in[2];  // market_odds     [B,6]

    long long n     = (long long)in_sizes[0];
    long long rows  = n / 6;
    long long pairs = rows / 2;

    init_acc_kernel<<<1, 1>>>();

    const int threads = 256;
    long long blocks = (pairs + threads - 1) / threads;
    if (blocks < 1) blocks = 1;
    betting_loss_kernel<<<(unsigned)blocks, threads>>>(probs, winners, odds,
                                                       pairs, rows);

    finalize_kernel<<<1, 1>>>((float*)d_out, out_size, 1.0 / (double)rows);
}

// round 5
// speedup vs baseline: 1.0593x; 1.0593x over previous
#include <cuda_runtime.h>

// ---------------------------------------------------------------------------
// BettingLoss, fused single-kernel version.
//   - smem-staged coalesced loads (kills the 3x L1tex wavefront amplification
//     of the 48B-strided per-thread float4 pattern)
//   - last-block finalize + accumulator reset (no init/finalize launches)
// 302 MB read / 12 B written -> DRAM-bound, floor ~45 us.
// ---------------------------------------------------------------------------

static __device__ double             g_sum_bet_ep;    // zero-init at load
static __device__ double             g_batch_profit;
static __device__ double             g_sum_maxprob;
static __device__ unsigned long long g_num_bets;
static __device__ unsigned int       g_block_count;   // self-wrapping ticket

constexpr int THREADS        = 256;
constexpr int ROWS_PER_TH    = 2;
constexpr int ROWS_PER_BLOCK = THREADS * ROWS_PER_TH;          // 512
constexpr int F4_PER_ARRAY   = ROWS_PER_BLOCK * 6 / 4;         // 768

// One race (6 traps), data already in registers/smem.
__device__ __forceinline__ void process_row(const float* __restrict__ p,
                                            const float* __restrict__ w,
                                            const float* __restrict__ o,
                                            float& ep_acc, float& pr_acc,
                                            float& mp_acc, int& nb)
{
    const float A   = 1.1f;    // ALPHA
    const float PAY = 0.019f;  // BET_PCT * (1 - COMMISSION)

    // Strict rounding (no FMA contraction) to match XLA's elementwise f32 at
    // the ep>0 decision boundary.
    float best = __fmul_rn(__fsub_rn(__fmul_rn(__fmul_rn(o[0], A), p[0]), 1.0f), PAY);
    float bo   = o[0];
    float bw   = w[0];
    float mx   = p[0];
    bool  valid = (o[0] > 0.0f);

#pragma unroll
    for (int i = 1; i < 6; ++i) {
        float ep = __fmul_rn(__fsub_rn(__fmul_rn(__fmul_rn(o[i], A), p[i]), 1.0f), PAY);
        if (ep > best) {       // strict '>' => first-max like jnp.argmax
            best = ep; bo = o[i]; bw = w[i];
        }
        mx    = fmaxf(mx, p[i]);
        valid = valid || (o[i] > 0.0f);
    }

    mp_acc += mx;              // fallback term: row-max prob for ALL rows

    if (valid && best > 0.0f) {
        ep_acc += best;
        nb     += 1;
        float win_profit = __fmul_rn(__fsub_rn(__fmul_rn(__fmul_rn(bo, A), 0.02f),
                                               0.02f), 0.95f);
        pr_acc += (bw > 0.5f) ? win_profit : -0.019f;
    }
}

__global__ void __launch_bounds__(THREADS)
betting_fused_kernel(const float* __restrict__ probs,
                     const float* __restrict__ winners,
                     const float* __restrict__ odds,
                     long long nF4,          // float4 count per array
                     float* __restrict__ out,
                     int out_size,
                     double invB)
{
    __shared__ float4 sP[F4_PER_ARRAY];
    __shared__ float4 sO[F4_PER_ARRAY];
    __shared__ float4 sW[F4_PER_ARRAY];
    __shared__ double re[8], rp[8], rm[8];
    __shared__ int    rn[8];

    const float4* __restrict__ P4 = (const float4*)probs;
    const float4* __restrict__ O4 = (const float4*)odds;
    const float4* __restrict__ W4 = (const float4*)winners;

    // ---- stage: fully coalesced global -> smem (3 float4 per thread/array,
    //      9 independent in-flight LDG.128 -> MLP ~9) ----
    long long tile = (long long)blockIdx.x * F4_PER_ARRAY;
    const float4 Z = make_float4(0.f, 0.f, 0.f, 0.f);
#pragma unroll
    for (int k = 0; k < F4_PER_ARRAY / THREADS; ++k) {   // 3 iters
        int  i = threadIdx.x + k * THREADS;
        long long g = tile + i;
        bool ok = (g < nF4);
        // zero-pad: fake rows have odds==0 -> invalid, maxprob contribution 0
        sP[i] = ok ? P4[g] : Z;
        sO[i] = ok ? O4[g] : Z;
        sW[i] = ok ? W4[g] : Z;
    }
    __syncthreads();

    // ---- compute: 2 rows per thread from smem ----
    const float* sp = (const float*)sP;
    const float* so = (const float*)sO;
    const float* sw = (const float*)sW;

    float ep_acc = 0.f, pr_acc = 0.f, mp_acc = 0.f;
    int   nb = 0;

    int base = threadIdx.x * 12;                // 2 rows * 6 floats
    process_row(sp + base,     sw + base,     so + base,
                ep_acc, pr_acc, mp_acc, nb);
    process_row(sp + base + 6, sw + base + 6, so + base + 6,
                ep_acc, pr_acc, mp_acc, nb);

    // ---- reduction: warp shuffle (double) -> smem -> 1 atomic set/block ----
    double de = (double)ep_acc, dp = (double)pr_acc, dm = (double)mp_acc;
    const unsigned full = 0xffffffffu;
#pragma unroll
    for (int off = 16; off > 0; off >>= 1) {
        de += __shfl_down_sync(full, de, off);
        dp += __shfl_down_sync(full, dp, off);
        dm += __shfl_down_sync(full, dm, off);
        nb += __shfl_down_sync(full, nb, off);
    }

    int warp = threadIdx.x >> 5;
    int lane = threadIdx.x & 31;
    if (lane == 0) { re[warp] = de; rp[warp] = dp; rm[warp] = dm; rn[warp] = nb; }
    __syncthreads();

    if (warp == 0) {
        de = (lane < 8) ? re[lane] : 0.0;
        dp = (lane < 8) ? rp[lane] : 0.0;
        dm = (lane < 8) ? rm[lane] : 0.0;
        nb = (lane < 8) ? rn[lane] : 0;
#pragma unroll
        for (int off = 4; off > 0; off >>= 1) {
            de += __shfl_down_sync(full, de, off);
            dp += __shfl_down_sync(full, dp, off);
            dm += __shfl_down_sync(full, dm, off);
            nb += __shfl_down_sync(full, nb, off);
        }
        if (lane == 0) {
            atomicAdd(&g_sum_bet_ep,   de);
            atomicAdd(&g_batch_profit, dp);
            atomicAdd(&g_sum_maxprob,  dm);
            atomicAdd(&g_num_bets, (unsigned long long)nb);

            // ---- last-block finalize + reset (graph-replay safe) ----
            __threadfence();
            unsigned ticket = atomicInc(&g_block_count, gridDim.x - 1); // wraps to 0
            if (ticket == gridDim.x - 1) {
                __threadfence();
                double e  = atomicAdd(&g_sum_bet_ep,   0.0);
                double p  = atomicAdd(&g_batch_profit, 0.0);
                double m  = atomicAdd(&g_sum_maxprob,  0.0);
                unsigned long long cnt = atomicAdd(&g_num_bets, 0ull);

                double total = (cnt > 0ull) ? e : -(m * invB) * 0.1;
                out[0] = (float)(-(total * invB));            // loss
                if (out_size >= 3) {
                    out[1] = (float)p;                        // batch_profit
                    out[2] = (float)cnt;                      // num_bets
                }
                // reset accumulators for the next graph replay
                atomicExch((unsigned long long*)&g_sum_bet_ep,   0ull);
                atomicExch((unsigned long long*)&g_batch_profit, 0ull);
                atomicExch((unsigned long long*)&g_sum_maxprob,  0ull);
                atomicExch(&g_num_bets, 0ull);
                // g_block_count already wrapped to 0 by atomicInc
            }
        }
    }
}

extern "C" void kernel_launch(void* const* d_in, const int* in_sizes, int n_in,
                              void* d_out, int out_size)
{
    const float* probs   = (const float*)d_in[0];  // predicted_probs [B,6]
    const float* winners = (const float*)d_in[1];  // true_winners    [B,6]
    const float* odds    = (const float*)d_in[2];  // market_odds     [B,6]

    long long n    = (long long)in_sizes[0];
    long long rows = n / 6;
    long long nF4  = n / 4;                        // n = rows*6, divisible by 4
                                                   // for even rows; pad handled
    long long blocks = (rows + ROWS_PER_BLOCK - 1) / ROWS_PER_BLOCK;
    if (blocks < 1) blocks = 1;

    betting_fused_kernel<<<(unsigned)blocks, THREADS>>>(
        probs, winners, odds, nF4, (float*)d_out, out_size,
        1.0 / (double)rows);
}

// round 6
// speedup vs baseline: 1.4493x; 1.3681x over previous
#include <cuda_runtime.h>

// ---------------------------------------------------------------------------
// BettingLoss, persistent double-buffered cp.async pipeline.
// R5 ncu showed DRAM=42.8% with nothing saturated: short-lived CTAs serialized
// load/compute phases -> ~50% DRAM duty cycle. Fix: persistent blocks, 2-stage
// cp.async pipeline so loads for tile k+1 overlap compute of tile k.
// ---------------------------------------------------------------------------

static __device__ double             g_sum_bet_ep;    // zero-init at load,
static __device__ double             g_batch_profit;  // reset by last block
static __device__ double             g_sum_maxprob;
static __device__ unsigned long long g_num_bets;
static __device__ unsigned int       g_block_count;   // self-wrapping ticket

constexpr int THREADS   = 256;
constexpr int TILE_ROWS = 256;                        // rows per tile
constexpr int F4S       = TILE_ROWS * 6 / 4;          // 384 float4 per array

// One race (6 traps) from smem.
__device__ __forceinline__ void process_row(const float* __restrict__ p,
                                            const float* __restrict__ w,
                                            const float* __restrict__ o,
                                            float& ep_acc, float& pr_acc,
                                            float& mp_acc, int& nb)
{
    const float A   = 1.1f;    // ALPHA
    const float PAY = 0.019f;  // BET_PCT * (1 - COMMISSION)

    // Strict rounding (no FMA contraction) to match XLA f32 at the ep>0 edge.
    float best = __fmul_rn(__fsub_rn(__fmul_rn(__fmul_rn(o[0], A), p[0]), 1.0f), PAY);
    float bo   = o[0];
    float bw   = w[0];
    float mx   = p[0];
    bool  valid = (o[0] > 0.0f);

#pragma unroll
    for (int i = 1; i < 6; ++i) {
        float ep = __fmul_rn(__fsub_rn(__fmul_rn(__fmul_rn(o[i], A), p[i]), 1.0f), PAY);
        if (ep > best) {       // strict '>' => first-max like jnp.argmax
            best = ep; bo = o[i]; bw = w[i];
        }
        mx    = fmaxf(mx, p[i]);
        valid = valid || (o[i] > 0.0f);
    }

    mp_acc += mx;              // fallback term needs row-max for ALL rows

    if (valid && best > 0.0f) {
        ep_acc += best;
        nb     += 1;
        float win_profit = __fmul_rn(__fsub_rn(__fmul_rn(__fmul_rn(bo, A), 0.02f),
                                               0.02f), 0.95f);
        pr_acc += (bw > 0.5f) ? win_profit : -0.019f;
    }
}

// Issue one tile's worth of cp.async (3 arrays x 384 float4) into `stage`,
// then commit the group. OOB elements zero-fill (src-size = 0).
__device__ __forceinline__ void prefetch_tile(unsigned sbase, int stage,
                                              const float4* __restrict__ P4,
                                              const float4* __restrict__ O4,
                                              const float4* __restrict__ W4,
                                              long long t, long long ntiles,
                                              long long nF4, int tid)
{
    long long base = t * (long long)F4S;
    bool tin = (t < ntiles);
    const float4* gs[3] = {P4, O4, W4};
#pragma unroll
    for (int a = 0; a < 3; ++a) {
        const float4* g = gs[a];
        // element 1: i = tid (always < 384)
        {
            long long gi  = base + tid;
            bool p        = tin && (gi < nF4);
            const void* s = p ? (const void*)(g + gi) : (const void*)g;
            unsigned dst  = sbase + (unsigned)(((stage * 3 + a) * F4S + tid) * 16);
            int sz        = p ? 16 : 0;
            asm volatile("cp.async.cg.shared.global [%0], [%1], 16, %2;"
                         :: "r"(dst), "l"(s), "r"(sz));
        }
        // element 2: i = tid + 256 (only tid < 128)
        if (tid < F4S - THREADS) {
            long long gi  = base + tid + THREADS;
            bool p        = tin && (gi < nF4);
            const void* s = p ? (const void*)(g + gi) : (const void*)g;
            unsigned dst  = sbase + (unsigned)(((stage * 3 + a) * F4S + tid + THREADS) * 16);
            int sz        = p ? 16 : 0;
            asm volatile("cp.async.cg.shared.global [%0], [%1], 16, %2;"
                         :: "r"(dst), "l"(s), "r"(sz));
        }
    }
    asm volatile("cp.async.commit_group;");
}

__global__ void __launch_bounds__(THREADS)
betting_pipe_kernel(const float* __restrict__ probs,
                    const float* __restrict__ winners,
                    const float* __restrict__ odds,
                    long long nF4, long long ntiles,
                    float* __restrict__ out, int out_size, double invB)
{
    __shared__ float4 sbuf[2][3][F4S];                // 36,864 B
    __shared__ double re[8], rp[8], rm[8];
    __shared__ int    rn[8];

    const float4* __restrict__ P4 = (const float4*)probs;
    const float4* __restrict__ O4 = (const float4*)odds;
    const float4* __restrict__ W4 = (const float4*)winners;

    const int tid = threadIdx.x;
    unsigned sbase = (unsigned)__cvta_generic_to_shared(&sbuf[0][0][0]);
    float* S = (float*)&sbuf[0][0][0];

    const long long gstride = gridDim.x;
    long long t = blockIdx.x;

    // prologue: fill both stages
    prefetch_tile(sbase, 0, P4, O4, W4, t,           ntiles, nF4, tid);
    prefetch_tile(sbase, 1, P4, O4, W4, t + gstride, ntiles, nF4, tid);

    double de = 0.0, dp = 0.0, dm = 0.0;
    int    nb = 0;
    int    stage = 0;

    for (; t < ntiles; t += gstride) {
        asm volatile("cp.async.wait_group 1;" ::: "memory");
        __syncthreads();

        // compute my row of this tile (data layout: [stage][array][row*6])
        const float* sp = S + (stage * 3 + 0) * F4S * 4 + tid * 6;
        const float* so = S + (stage * 3 + 1) * F4S * 4 + tid * 6;
        const float* sw = S + (stage * 3 + 2) * F4S * 4 + tid * 6;

        float ep = 0.f, pr = 0.f, mp = 0.f;
        int   n1 = 0;
        process_row(sp, sw, so, ep, pr, mp, n1);
        de += (double)ep; dp += (double)pr; dm += (double)mp; nb += n1;

        __syncthreads();   // everyone done reading `stage` before refilling it
        prefetch_tile(sbase, stage, P4, O4, W4, t + 2 * gstride, ntiles, nF4, tid);
        stage ^= 1;
    }
    asm volatile("cp.async.wait_group 0;" ::: "memory");

    // ---- block reduction: warp shuffle (double) -> smem -> 1 atomic set ----
    const unsigned full = 0xffffffffu;
#pragma unroll
    for (int off = 16; off > 0; off >>= 1) {
        de += __shfl_down_sync(full, de, off);
        dp += __shfl_down_sync(full, dp, off);
        dm += __shfl_down_sync(full, dm, off);
        nb += __shfl_down_sync(full, nb, off);
    }
    int warp = tid >> 5;
    int lane = tid & 31;
    if (lane == 0) { re[warp] = de; rp[warp] = dp; rm[warp] = dm; rn[warp] = nb; }
    __syncthreads();

    if (warp == 0) {
        de = (lane < 8) ? re[lane] : 0.0;
        dp = (lane < 8) ? rp[lane] : 0.0;
        dm = (lane < 8) ? rm[lane] : 0.0;
        nb = (lane < 8) ? rn[lane] : 0;
#pragma unroll
        for (int off = 4; off > 0; off >>= 1) {
            de += __shfl_down_sync(full, de, off);
            dp += __shfl_down_sync(full, dp, off);
            dm += __shfl_down_sync(full, dm, off);
            nb += __shfl_down_sync(full, nb, off);
        }
        if (lane == 0) {
            atomicAdd(&g_sum_bet_ep,   de);
            atomicAdd(&g_batch_profit, dp);
            atomicAdd(&g_sum_maxprob,  dm);
            atomicAdd(&g_num_bets, (unsigned long long)nb);

            // ---- last-block finalize + reset (graph-replay safe) ----
            __threadfence();
            unsigned ticket = atomicInc(&g_block_count, gridDim.x - 1);
            if (ticket == gridDim.x - 1) {
                __threadfence();
                double e = atomicAdd(&g_sum_bet_ep,   0.0);
                double p = atomicAdd(&g_batch_profit, 0.0);
                double m = atomicAdd(&g_sum_maxprob,  0.0);
                unsigned long long cnt = atomicAdd(&g_num_bets, 0ull);

                double total = (cnt > 0ull) ? e : -(m * invB) * 0.1;
                out[0] = (float)(-(total * invB));            // loss
                if (out_size >= 3) {
                    out[1] = (float)p;                        // batch_profit
                    out[2] = (float)cnt;                      // num_bets
                }
                atomicExch((unsigned long long*)&g_sum_bet_ep,   0ull);
                atomicExch((unsigned long long*)&g_batch_profit, 0ull);
                atomicExch((unsigned long long*)&g_sum_maxprob,  0ull);
                atomicExch(&g_num_bets, 0ull);
                // g_block_count wrapped to 0 by atomicInc
            }
        }
    }
}

extern "C" void kernel_launch(void* const* d_in, const int* in_sizes, int n_in,
                              void* d_out, int out_size)
{
    const float* probs   = (const float*)d_in[0];  // predicted_probs [B,6]
    const float* winners = (const float*)d_in[1];  // true_winners    [B,6]
    const float* odds    = (const float*)d_in[2];  // market_odds     [B,6]

    long long n      = (long long)in_sizes[0];
    long long rows   = n / 6;
    long long nF4    = n / 4;
    long long ntiles = (rows + TILE_ROWS - 1) / TILE_ROWS;

    long long blocks = 148LL * 6;                  // 6 CTAs/SM, one wave
    if (blocks > ntiles) blocks = ntiles;
    if (blocks < 1) blocks = 1;

    betting_pipe_kernel<<<(unsigned)blocks, THREADS>>>(
        probs, winners, odds, nF4, ntiles,
        (float*)d_out, out_size, 1.0 / (double)rows);
}

// round 10
// speedup vs baseline: 1.5075x; 1.0402x over previous
#include <cuda_runtime.h>

// ---------------------------------------------------------------------------
// BettingLoss, persistent 3-stage cp.async pipeline, ONE barrier per iter.
// R6: 2-stage pipeline reached DRAM=60.7% (66us). Residual = latency exposure:
// wait_group covered only 1 iteration. Now: 3-stage ring, refill right after
// the single barrier (the barrier proves last iter's stage is fully consumed),
// wait_group 1 -> waits on the group issued TWO iterations ago.
// ---------------------------------------------------------------------------

static __device__ double             g_sum_bet_ep;    // zero-init at load,
static __device__ double             g_batch_profit;  // reset by last block
static __device__ double             g_sum_maxprob;
static __device__ unsigned long long g_num_bets;
static __device__ unsigned int       g_block_count;   // self-wrapping ticket

constexpr int THREADS   = 256;
constexpr int TILE_ROWS = 256;                        // rows per tile
constexpr int F4S       = TILE_ROWS * 6 / 4;          // 384 float4 per array
constexpr int STAGES    = 3;
constexpr int STAGE_B   = 3 * F4S * 16;               // bytes per stage (18432)

// One race (6 traps) from smem.
__device__ __forceinline__ void process_row(const float* __restrict__ p,
                                            const float* __restrict__ w,
                                            const float* __restrict__ o,
                                            float& ep_acc, float& pr_acc,
                                            float& mp_acc, int& nb)
{
    const float A   = 1.1f;    // ALPHA
    const float PAY = 0.019f;  // BET_PCT * (1 - COMMISSION)

    // Strict rounding (no FMA contraction) to match XLA f32 at the ep>0 edge.
    float best = __fmul_rn(__fsub_rn(__fmul_rn(__fmul_rn(o[0], A), p[0]), 1.0f), PAY);
    float bo   = o[0];
    float bw   = w[0];
    float mx   = p[0];
    bool  valid = (o[0] > 0.0f);

#pragma unroll
    for (int i = 1; i < 6; ++i) {
        float ep = __fmul_rn(__fsub_rn(__fmul_rn(__fmul_rn(o[i], A), p[i]), 1.0f), PAY);
        if (ep > best) {       // strict '>' => first-max like jnp.argmax
            best = ep; bo = o[i]; bw = w[i];
        }
        mx    = fmaxf(mx, p[i]);
        valid = valid || (o[i] > 0.0f);
    }

    mp_acc += mx;              // fallback term needs row-max for ALL rows

    if (valid && best > 0.0f) {
        ep_acc += best;
        nb     += 1;
        float win_profit = __fmul_rn(__fsub_rn(__fmul_rn(__fmul_rn(bo, A), 0.02f),
                                               0.02f), 0.95f);
        pr_acc += (bw > 0.5f) ? win_profit : -0.019f;
    }
}

// Issue one tile (3 arrays x 384 float4) into stage s, commit the group.
// OOB -> src-size 0 zero-fill (zero rows: odds==0 => invalid, no contribution).
__device__ __forceinline__ void prefetch_tile(unsigned sbase, int s,
                                              const float4* __restrict__ P4,
                                              const float4* __restrict__ O4,
                                              const float4* __restrict__ W4,
                                              long long t, long long ntiles,
                                              long long nF4, int tid)
{
    long long base = t * (long long)F4S;
    bool tin = (t < ntiles);
    unsigned sdst = sbase + (unsigned)(s * STAGE_B) + (unsigned)(tid * 16);
    const float4* gs[3] = {P4, O4, W4};
#pragma unroll
    for (int a = 0; a < 3; ++a) {
        const float4* g = gs[a];
        {
            long long gi  = base + tid;
            bool p        = tin && (gi < nF4);
            const void* src = p ? (const void*)(g + gi) : (const void*)g;
            unsigned dst  = sdst + (unsigned)(a * F4S * 16);
            int sz        = p ? 16 : 0;
            asm volatile("cp.async.cg.shared.global [%0], [%1], 16, %2;"
                         :: "r"(dst), "l"(src), "r"(sz));
        }
        if (tid < F4S - THREADS) {     // second element: tid < 128
            long long gi  = base + tid + THREADS;
            bool p        = tin && (gi < nF4);
            const void* src = p ? (const void*)(g + gi) : (const void*)g;
            unsigned dst  = sdst + (unsigned)(a * F4S * 16 + THREADS * 16);
            int sz        = p ? 16 : 0;
            asm volatile("cp.async.cg.shared.global [%0], [%1], 16, %2;"
                         :: "r"(dst), "l"(src), "r"(sz));
        }
    }
    asm volatile("cp.async.commit_group;");
}

__global__ void __launch_bounds__(THREADS)
betting_pipe3_kernel(const float* __restrict__ probs,
                     const float* __restrict__ winners,
                     const float* __restrict__ odds,
                     long long nF4, long long ntiles,
                     float* __restrict__ out, int out_size, double invB)
{
    __shared__ float4 sbuf[STAGES][3][F4S];           // 55,296 B
    __shared__ double re[8], rp[8], rm[8];
    __shared__ int    rn[8];

    const float4* __restrict__ P4 = (const float4*)probs;
    const float4* __restrict__ O4 = (const float4*)odds;
    const float4* __restrict__ W4 = (const float4*)winners;

    const int tid = threadIdx.x;
    unsigned sbase = (unsigned)__cvta_generic_to_shared(&sbuf[0][0][0]);
    const float* S = (const float*)&sbuf[0][0][0];

    const long long gstride = gridDim.x;
    long long t = blockIdx.x;

    // prologue: fill stages 0 and 1 (tiles t, t+gstride)
    prefetch_tile(sbase, 0, P4, O4, W4, t,           ntiles, nF4, tid);
    prefetch_tile(sbase, 1, P4, O4, W4, t + gstride, ntiles, nF4, tid);

    double de = 0.0, dp = 0.0, dm = 0.0;
    int    nb = 0;
    int    cs = 0;                                    // compute stage
    int    fs = 2;                                    // fill stage

    for (long long k = 0; t < ntiles; t += gstride, ++k) {
        // waits on the group issued two iterations ago (pipeline depth 2)
        asm volatile("cp.async.wait_group 1;" ::: "memory");
        __syncthreads();   // data visible; also proves last iter's stage is
                           // fully consumed by ALL threads -> safe to refill fs

        prefetch_tile(sbase, fs, P4, O4, W4, t + 2 * gstride, ntiles, nF4, tid);

        const float* sp = S + (cs * 3 + 0) * (F4S * 4) + tid * 6;
        const float* so = S + (cs * 3 + 1) * (F4S * 4) + tid * 6;
        const float* sw = S + (cs * 3 + 2) * (F4S * 4) + tid * 6;

        float ep = 0.f, pr = 0.f, mp = 0.f;
        int   n1 = 0;
        process_row(sp, sw, so, ep, pr, mp, n1);
        de += (double)ep; dp += (double)pr; dm += (double)mp; nb += n1;

        cs = (cs == STAGES - 1) ? 0 : cs + 1;
        fs = (fs == STAGES - 1) ? 0 : fs + 1;
    }
    asm volatile("cp.async.wait_group 0;" ::: "memory");

    // ---- block reduction: warp shuffle (double) -> smem -> 1 atomic set ----
    const unsigned full = 0xffffffffu;
#pragma unroll
    for (int off = 16; off > 0; off >>= 1) {
        de += __shfl_down_sync(full, de, off);
        dp += __shfl_down_sync(full, dp, off);
        dm += __shfl_down_sync(full, dm, off);
        nb += __shfl_down_sync(full, nb, off);
    }
    int warp = tid >> 5;
    int lane = tid & 31;
    if (lane == 0) { re[warp] = de; rp[warp] = dp; rm[warp] = dm; rn[warp] = nb; }
    __syncthreads();

    if (warp == 0) {
        de = (lane < 8) ? re[lane] : 0.0;
        dp = (lane < 8) ? rp[lane] : 0.0;
        dm = (lane < 8) ? rm[lane] : 0.0;
        nb = (lane < 8) ? rn[lane] : 0;
#pragma unroll
        for (int off = 4; off > 0; off >>= 1) {
            de += __shfl_down_sync(full, de, off);
            dp += __shfl_down_sync(full, dp, off);
            dm += __shfl_down_sync(full, dm, off);
            nb += __shfl_down_sync(full, nb, off);
        }
        if (lane == 0) {
            atomicAdd(&g_sum_bet_ep,   de);
            atomicAdd(&g_batch_profit, dp);
            atomicAdd(&g_sum_maxprob,  dm);
            atomicAdd(&g_num_bets, (unsigned long long)nb);

            // ---- last-block finalize + reset (graph-replay safe) ----
            __threadfence();
            unsigned ticket = atomicInc(&g_block_count, gridDim.x - 1);
            if (ticket == gridDim.x - 1) {
                __threadfence();
                double e = atomicAdd(&g_sum_bet_ep,   0.0);
                double p = atomicAdd(&g_batch_profit, 0.0);
                double m = atomicAdd(&g_sum_maxprob,  0.0);
                unsigned long long cnt = atomicAdd(&g_num_bets, 0ull);

                double total = (cnt > 0ull) ? e : -(m * invB) * 0.1;
                out[0] = (float)(-(total * invB));            // loss
                if (out_size >= 3) {
                    out[1] = (float)p;                        // batch_profit
                    out[2] = (float)cnt;                      // num_bets
                }
                atomicExch((unsigned long long*)&g_sum_bet_ep,   0ull);
                atomicExch((unsigned long long*)&g_batch_profit, 0ull);
                atomicExch((unsigned long long*)&g_sum_maxprob,  0ull);
                atomicExch(&g_num_bets, 0ull);
                // g_block_count wrapped to 0 by atomicInc
            }
        }
    }
}

extern "C" void kernel_launch(void* const* d_in, const int* in_sizes, int n_in,
                              void* d_out, int out_size)
{
    const float* probs   = (const float*)d_in[0];  // predicted_probs [B,6]
    const float* winners = (const float*)d_in[1];  // true_winners    [B,6]
    const float* odds    = (const float*)d_in[2];  // market_odds     [B,6]

    long long n      = (long long)in_sizes[0];
    long long rows   = n / 6;
    long long nF4    = n / 4;
    long long ntiles = (rows + TILE_ROWS - 1) / TILE_ROWS;

    long long blocks = 148LL * 4;                  // 4 CTAs/SM (55.3KB smem)
    if (blocks > ntiles) blocks = ntiles;
    if (blocks < 1) blocks = 1;

    betting_pipe3_kernel<<<(unsigned)blocks, THREADS>>>(
        probs, winners, odds, nF4, ntiles,
        (float*)d_out, out_size, 1.0 / (double)rows);
}

// round 12
// speedup vs baseline: 1.5091x; 1.0010x over previous
#include <cuda_runtime.h>

// ---------------------------------------------------------------------------
// BettingLoss, persistent TMA-bulk (UBLKCP) 3-stage pipeline.
// R6 post-mortem: cp.async producer plateaued at DRAM=62% with NO unit
// saturated => request-generation bound (144 LDGSTS warp-ops/tile competing
// with compute for issue). Fix: tid0 issues 3 cp.async.bulk per 36.9KB tile;
// the copy engine generates requests, SM issue slots go to compute only.
// ---------------------------------------------------------------------------

static __device__ double             g_sum_bet_ep;    // zero-init at load,
static __device__ double             g_batch_profit;  // reset by last block
static __device__ double             g_sum_maxprob;
static __device__ unsigned long long g_num_bets;
static __device__ unsigned int       g_block_count;   // self-wrapping ticket

constexpr int      THREADS    = 512;
constexpr int      TILE_ROWS  = 512;                  // rows per tile
constexpr unsigned ARR_BYTES  = TILE_ROWS * 24u;      // 12288 B per array
constexpr unsigned STAGE_B    = 3u * ARR_BYTES;       // 36864 B per stage
constexpr int      STAGES     = 3;
constexpr unsigned SMEM_DYN   = STAGES * STAGE_B;     // 110592 B

// One race (6 traps) from smem.
__device__ __forceinline__ void process_row(const float* __restrict__ p,
                                            const float* __restrict__ w,
                                            const float* __restrict__ o,
                                            float& ep_acc, float& pr_acc,
                                            float& mp_acc, int& nb)
{
    const float A   = 1.1f;    // ALPHA
    const float PAY = 0.019f;  // BET_PCT * (1 - COMMISSION)

    // Strict rounding (no FMA contraction) to match XLA f32 at the ep>0 edge.
    float best = __fmul_rn(__fsub_rn(__fmul_rn(__fmul_rn(o[0], A), p[0]), 1.0f), PAY);
    float bo   = o[0];
    float bw   = w[0];
    float mx   = p[0];
    bool  valid = (o[0] > 0.0f);

#pragma unroll
    for (int i = 1; i < 6; ++i) {
        float ep = __fmul_rn(__fsub_rn(__fmul_rn(__fmul_rn(o[i], A), p[i]), 1.0f), PAY);
        if (ep > best) {       // strict '>' => first-max like jnp.argmax
            best = ep; bo = o[i]; bw = w[i];
        }
        mx    = fmaxf(mx, p[i]);
        valid = valid || (o[i] > 0.0f);
    }

    mp_acc += mx;              // fallback term needs row-max for ALL rows

    if (valid && best > 0.0f) {
        ep_acc += best;
        nb     += 1;
        float win_profit = __fmul_rn(__fsub_rn(__fmul_rn(__fmul_rn(bo, A), 0.02f),
                                               0.02f), 0.95f);
        pr_acc += (bw > 0.5f) ? win_profit : -0.019f;
    }
}

// tid0 only: arm the tx-barrier and issue 3 bulk copies (one per array).
__device__ __forceinline__ void tma_fill(unsigned mbar, unsigned sdst,
                                         const char* __restrict__ pB,
                                         const char* __restrict__ oB,
                                         const char* __restrict__ wB,
                                         long long tile)
{
    long long off = tile * (long long)ARR_BYTES;
    asm volatile("mbarrier.arrive.expect_tx.shared.b64 _, [%0], %1;"
                 :: "r"(mbar), "r"(STAGE_B) : "memory");
    asm volatile("cp.async.bulk.shared::cluster.global.mbarrier::complete_tx::bytes"
                 " [%0], [%1], %2, [%3];"
                 :: "r"(sdst),                 "l"(pB + off), "r"(ARR_BYTES),
                    "r"(mbar) : "memory");
    asm volatile("cp.async.bulk.shared::cluster.global.mbarrier::complete_tx::bytes"
                 " [%0], [%1], %2, [%3];"
                 :: "r"(sdst + ARR_BYTES),     "l"(oB + off), "r"(ARR_BYTES),
                    "r"(mbar) : "memory");
    asm volatile("cp.async.bulk.shared::cluster.global.mbarrier::complete_tx::bytes"
                 " [%0], [%1], %2, [%3];"
                 :: "r"(sdst + 2 * ARR_BYTES), "l"(wB + off), "r"(ARR_BYTES),
                    "r"(mbar) : "memory");
}

__device__ __forceinline__ void mbar_wait(unsigned mbar, unsigned parity)
{
    asm volatile(
        "{\n\t"
        ".reg .pred P;\n\t"
        "WAIT_%=:\n\t"
        "mbarrier.try_wait.parity.acquire.cta.shared::cta.b64 P, [%0], %1, 0x989680;\n\t"
        "@P bra DONE_%=;\n\t"
        "bra WAIT_%=;\n\t"
        "DONE_%=:\n\t"
        "}" :: "r"(mbar), "r"(parity) : "memory");
}

extern __shared__ float s_dyn[];                      // STAGES * 36864 B

__global__ void __launch_bounds__(THREADS)
betting_tma_kernel(const float* __restrict__ probs,
                   const float* __restrict__ winners,
                   const float* __restrict__ odds,
                   long long ntiles, long long rows,
                   float* __restrict__ out, int out_size, double invB)
{
    __shared__ __align__(8) unsigned long long s_mbar[STAGES];  // full barriers
    __shared__ double re[16], rp[16], rm[16];
    __shared__ int    rn[16];

    const int tid = threadIdx.x;
    unsigned sbase = (unsigned)__cvta_generic_to_shared(s_dyn);
    unsigned mbase = (unsigned)__cvta_generic_to_shared(s_mbar);

    const char* pB = (const char*)probs;
    const char* oB = (const char*)odds;
    const char* wB = (const char*)winners;

    if (tid == 0) {
#pragma unroll
        for (int s = 0; s < STAGES; ++s)
            asm volatile("mbarrier.init.shared.b64 [%0], 1;"
                         :: "r"(mbase + 8u * s) : "memory");
    }
    __syncthreads();
    asm volatile("fence.proxy.async.shared::cta;" ::: "memory");

    const long long g  = gridDim.x;
    const long long t0 = blockIdx.x;

    // prologue: fill all 3 stages
    if (tid == 0) {
#pragma unroll
        for (int k = 0; k < STAGES; ++k) {
            long long tk = t0 + (long long)k * g;
            if (tk < ntiles)
                tma_fill(mbase + 8u * k, sbase + (unsigned)k * STAGE_B,
                         pB, oB, wB, tk);
        }
    }

    double de = 0.0, dp = 0.0, dm = 0.0;
    int    nb = 0;

    // remainder rows (rows % TILE_ROWS), handled by block 0 via direct loads
    if (blockIdx.x == 0) {
        long long full = ntiles * TILE_ROWS;
        for (long long r = full + tid; r < rows; r += THREADS) {
            long long b6 = r * 6;
            float p[6], w[6], o[6];
#pragma unroll
            for (int i = 0; i < 6; ++i) {
                p[i] = probs[b6 + i]; w[i] = winners[b6 + i]; o[i] = odds[b6 + i];
            }
            float ep = 0.f, pr = 0.f, mp = 0.f; int n1 = 0;
            process_row(p, w, o, ep, pr, mp, n1);
            de += ep; dp += pr; dm += mp; nb += n1;
        }
    }

    int cs = 0;        // stage cursor
    unsigned cph = 0;  // phase parity for full barriers
    long long tnext = t0 + (long long)STAGES * g;

    for (long long t = t0; t < ntiles; t += g) {
        mbar_wait(mbase + 8u * cs, cph);

        const float* S  = s_dyn + (unsigned)cs * (STAGE_B / 4u);
        const float* sp = S + tid * 6;
        const float* so = S + (ARR_BYTES / 4u)     + tid * 6;
        const float* sw = S + (ARR_BYTES / 4u) * 2 + tid * 6;

        float ep = 0.f, pr = 0.f, mp = 0.f; int n1 = 0;
        process_row(sp, sw, so, ep, pr, mp, n1);
        de += (double)ep; dp += (double)pr; dm += (double)mp; nb += n1;

        __syncthreads();   // all threads done reading stage cs -> refill it
        if (tid == 0 && tnext < ntiles) {
            asm volatile("fence.proxy.async.shared::cta;" ::: "memory");
            tma_fill(mbase + 8u * cs, sbase + (unsigned)cs * STAGE_B,
                     pB, oB, wB, tnext);
        }
        tnext += g;
        cs = (cs == STAGES - 1) ? 0 : cs + 1;
        if (cs == 0) cph ^= 1u;
    }

    // ---- block reduction: warp shuffle (double) -> smem -> 1 atomic set ----
    const unsigned full_m = 0xffffffffu;
#pragma unroll
    for (int off = 16; off > 0; off >>= 1) {
        de += __shfl_down_sync(full_m, de, off);
        dp += __shfl_down_sync(full_m, dp, off);
        dm += __shfl_down_sync(full_m, dm, off);
        nb += __shfl_down_sync(full_m, nb, off);
    }
    int warp = tid >> 5;
    int lane = tid & 31;
    if (lane == 0) { re[warp] = de; rp[warp] = dp; rm[warp] = dm; rn[warp] = nb; }
    __syncthreads();

    if (warp == 0) {
        de = (lane < 16) ? re[lane] : 0.0;
        dp = (lane < 16) ? rp[lane] : 0.0;
        dm = (lane < 16) ? rm[lane] : 0.0;
        nb = (lane < 16) ? rn[lane] : 0;
#pragma unroll
        for (int off = 8; off > 0; off >>= 1) {
            de += __shfl_down_sync(full_m, de, off);
            dp += __shfl_down_sync(full_m, dp, off);
            dm += __shfl_down_sync(full_m, dm, off);
            nb += __shfl_down_sync(full_m, nb, off);
        }
        if (lane == 0) {
            atomicAdd(&g_sum_bet_ep,   de);
            atomicAdd(&g_batch_profit, dp);
            atomicAdd(&g_sum_maxprob,  dm);
            atomicAdd(&g_num_bets, (unsigned long long)nb);

            // ---- last-block finalize + reset (graph-replay safe) ----
            __threadfence();
            unsigned ticket = atomicInc(&g_block_count, gridDim.x - 1);
            if (ticket == gridDim.x - 1) {
                __threadfence();
                double e = atomicAdd(&g_sum_bet_ep,   0.0);
                double p = atomicAdd(&g_batch_profit, 0.0);
                double m = atomicAdd(&g_sum_maxprob,  0.0);
                unsigned long long cnt = atomicAdd(&g_num_bets, 0ull);

                double total = (cnt > 0ull) ? e : -(m * invB) * 0.1;
                out[0] = (float)(-(total * invB));            // loss
                if (out_size >= 3) {
                    out[1] = (float)p;                        // batch_profit
                    out[2] = (float)cnt;                      // num_bets
                }
                atomicExch((unsigned long long*)&g_sum_bet_ep,   0ull);
                atomicExch((unsigned long long*)&g_batch_profit, 0ull);
                atomicExch((unsigned long long*)&g_sum_maxprob,  0ull);
                atomicExch(&g_num_bets, 0ull);
                // g_block_count wrapped to 0 by atomicInc
            }
        }
    }
}

extern "C" void kernel_launch(void* const* d_in, const int* in_sizes, int n_in,
                              void* d_out, int out_size)
{
    const float* probs   = (const float*)d_in[0];  // predicted_probs [B,6]
    const float* winners = (const float*)d_in[1];  // true_winners    [B,6]
    const float* odds    = (const float*)d_in[2];  // market_odds     [B,6]

    long long n      = (long long)in_sizes[0];
    long long rows   = n / 6;
    long long ntiles = rows / TILE_ROWS;           // full tiles only

    static int attr_done = 0;
    if (!attr_done) {
        cudaFuncSetAttribute(betting_tma_kernel,
                             cudaFuncAttributeMaxDynamicSharedMemorySize,
                             (int)SMEM_DYN);
        attr_done = 1;
    }

    long long blocks = 148LL * 2;                  // 2 CTAs/SM (110.6KB each)
    if (blocks > ntiles) blocks = ntiles;
    if (blocks < 1) blocks = 1;

    betting_tma_kernel<<<(unsigned)blocks, THREADS, SMEM_DYN>>>(
        probs, winners, odds, ntiles, rows,
        (float*)d_out, out_size, 1.0 / (double)rows);
}